// round 5
// baseline (speedup 1.0000x reference)
#include <cuda_runtime.h>
#include <cstdio>

#define BB 2
#define HH 12
#define SS 2048
#define DH 64
#define DM 768
#define MM (BB * SS)                                   // 4096
#define ACT_ELEMS ((long long)BB * SS * DM)            // 3,145,728
#define QKV_ELEMS ((long long)BB * HH * SS * DH)       // 3,145,728
#define W_ELEMS ((long long)DM * DM)                   // 589,824
#define OUT_ELEMS ((long long)BB * SS * DM)            // 3,145,728
#define ATTN_ELEMS ((long long)BB * HH * SS * SS)      // 100,663,296

// Static device scratch (module-load allocated; no runtime allocs).
__device__ float g_q[3145728];
__device__ float g_k[3145728];
__device__ float g_v[3145728];
__device__ float g_ctx[3145728];

// Guarded global accessors: OOB becomes a benign no-op / zero instead of a fault.
__device__ __forceinline__ float gld(const float* __restrict__ p, long long i, long long n) {
    return (i >= 0 && i < n) ? __ldg(p + i) : 0.f;
}
__device__ __forceinline__ void gst(float* __restrict__ p, long long i, long long n, float v) {
    if (i >= 0 && i < n) p[i] = v;
}

// ---------------------------------------------------------------------------
// Projection GEMM: C(head layout) = A[M,K] @ W[N,K]^T + bias.
// DSTSEL: 0->g_q, 1->g_k, 2->g_v.
// ---------------------------------------------------------------------------
template <int DSTSEL>
__global__ void __launch_bounds__(256) proj_kernel(
    const float* __restrict__ A, const float* __restrict__ W,
    const float* __restrict__ bias)
{
    __shared__ float As[64][17];
    __shared__ float Ws[16][65];

    float* C = (DSTSEL == 0) ? g_q : (DSTSEL == 1) ? g_k : g_v;

    const int tx = threadIdx.x, ty = threadIdx.y;
    const int tid = ty * 16 + tx;
    const int row0 = blockIdx.y * 64;
    const int col0 = blockIdx.x * 64;

    float acc[4][4];
#pragma unroll
    for (int i = 0; i < 4; i++)
#pragma unroll
        for (int j = 0; j < 4; j++) acc[i][j] = 0.f;

    for (int k0 = 0; k0 < DM; k0 += 16) {
#pragma unroll
        for (int l = 0; l < 4; l++) {
            int idx = tid + l * 256;
            int m = idx >> 4;
            int k = idx & 15;
            As[m][k] = gld(A, (long long)(row0 + m) * DM + k0 + k, ACT_ELEMS);
            Ws[k][m] = gld(W, (long long)(col0 + m) * DM + k0 + k, W_ELEMS);
        }
        __syncthreads();
#pragma unroll
        for (int k = 0; k < 16; k++) {
            float a[4], w[4];
#pragma unroll
            for (int i = 0; i < 4; i++) a[i] = As[ty * 4 + i][k];
#pragma unroll
            for (int j = 0; j < 4; j++) w[j] = Ws[k][tx * 4 + j];
#pragma unroll
            for (int i = 0; i < 4; i++)
#pragma unroll
                for (int j = 0; j < 4; j++) acc[i][j] += a[i] * w[j];
        }
        __syncthreads();
    }

#pragma unroll
    for (int i = 0; i < 4; i++) {
        int gm = row0 + ty * 4 + i;
        int b = gm >> 11, s = gm & 2047;
#pragma unroll
        for (int j = 0; j < 4; j++) {
            int gn = col0 + tx * 4 + j;
            int h = gn >> 6, d = gn & 63;
            long long ci = (((long long)(b * HH + h)) * SS + s) * DH + d;
            gst(C, ci, QKV_ELEMS, acc[i][j] + gld(bias, gn, DM));
        }
    }
}

// ---------------------------------------------------------------------------
// Output projection: out = gather(g_ctx) @ W_o^T + b_o.
// ---------------------------------------------------------------------------
__global__ void __launch_bounds__(256) out_proj_kernel(
    const float* __restrict__ W, const float* __restrict__ bias,
    float* __restrict__ out)
{
    __shared__ float As[64][17];
    __shared__ float Ws[16][65];

    const int tx = threadIdx.x, ty = threadIdx.y;
    const int tid = ty * 16 + tx;
    const int row0 = blockIdx.y * 64;
    const int col0 = blockIdx.x * 64;

    float acc[4][4];
#pragma unroll
    for (int i = 0; i < 4; i++)
#pragma unroll
        for (int j = 0; j < 4; j++) acc[i][j] = 0.f;

    for (int k0 = 0; k0 < DM; k0 += 16) {
#pragma unroll
        for (int l = 0; l < 4; l++) {
            int idx = tid + l * 256;
            int m = idx >> 4;
            int k = idx & 15;
            int gm = row0 + m;
            int gk = k0 + k;
            int b = gm >> 11, s = gm & 2047;
            int h = gk >> 6, d = gk & 63;
            long long ai = (((long long)(b * HH + h)) * SS + s) * DH + d;
            As[m][k] = (ai >= 0 && ai < QKV_ELEMS) ? g_ctx[ai] : 0.f;
            Ws[k][m] = gld(W, (long long)(col0 + m) * DM + gk, W_ELEMS);
        }
        __syncthreads();
#pragma unroll
        for (int k = 0; k < 16; k++) {
            float a[4], w[4];
#pragma unroll
            for (int i = 0; i < 4; i++) a[i] = As[ty * 4 + i][k];
#pragma unroll
            for (int j = 0; j < 4; j++) w[j] = Ws[k][tx * 4 + j];
#pragma unroll
            for (int i = 0; i < 4; i++)
#pragma unroll
                for (int j = 0; j < 4; j++) acc[i][j] += a[i] * w[j];
        }
        __syncthreads();
    }

#pragma unroll
    for (int i = 0; i < 4; i++) {
        int gm = row0 + ty * 4 + i;
#pragma unroll
        for (int j = 0; j < 4; j++) {
            int gn = col0 + tx * 4 + j;
            gst(out, (long long)gm * DM + gn, OUT_ELEMS, acc[i][j] + gld(bias, gn, DM));
        }
    }
}

// ---------------------------------------------------------------------------
// Scores: attn[bh,i,j] = dot(Q[i,:], K[j,:]) / 8.  grid (S/64, S/64, B*H).
// ---------------------------------------------------------------------------
__global__ void __launch_bounds__(256) scores_kernel(float* __restrict__ attn)
{
    __shared__ float Qs[64][65];
    __shared__ float Ks[64][65];

    const int tx = threadIdx.x, ty = threadIdx.y;
    const int tid = ty * 16 + tx;
    const int bh = blockIdx.z;
    const int row0 = blockIdx.y * 64;
    const int col0 = blockIdx.x * 64;
    const long long base = (long long)bh * SS * DH;

#pragma unroll
    for (int l = 0; l < 16; l++) {
        int idx = tid + l * 256;
        int r = idx >> 6, c = idx & 63;
        Qs[r][c] = gld(g_q, base + (long long)(row0 + r) * DH + c, QKV_ELEMS);
        Ks[r][c] = gld(g_k, base + (long long)(col0 + r) * DH + c, QKV_ELEMS);
    }
    __syncthreads();

    float acc[4][4];
#pragma unroll
    for (int i = 0; i < 4; i++)
#pragma unroll
        for (int j = 0; j < 4; j++) acc[i][j] = 0.f;

#pragma unroll
    for (int k = 0; k < 64; k++) {
        float a[4], b[4];
#pragma unroll
        for (int i = 0; i < 4; i++) a[i] = Qs[ty * 4 + i][k];
#pragma unroll
        for (int j = 0; j < 4; j++) b[j] = Ks[tx * 4 + j][k];
#pragma unroll
        for (int i = 0; i < 4; i++)
#pragma unroll
            for (int j = 0; j < 4; j++) acc[i][j] += a[i] * b[j];
    }

#pragma unroll
    for (int i = 0; i < 4; i++) {
        long long rbase = ((long long)bh * SS + row0 + ty * 4 + i) * SS + col0;
#pragma unroll
        for (int j = 0; j < 4; j++)
            gst(attn, rbase + tx * 4 + j, ATTN_ELEMS, acc[i][j] * 0.125f);
    }
}

// ---------------------------------------------------------------------------
// Row softmax over 2048 cols; one 256-thread block per row.
// ---------------------------------------------------------------------------
__global__ void __launch_bounds__(256) softmax_kernel(float* __restrict__ attn)
{
    __shared__ float red[8];
    const long long rbase = (long long)blockIdx.x * SS;
    const int tid = threadIdx.x;

    float v[8];
#pragma unroll
    for (int i = 0; i < 8; i++) v[i] = gld(attn, rbase + tid + i * 256, ATTN_ELEMS);

    float m = v[0];
#pragma unroll
    for (int i = 1; i < 8; i++) m = fmaxf(m, v[i]);
#pragma unroll
    for (int o = 16; o > 0; o >>= 1) m = fmaxf(m, __shfl_xor_sync(0xFFFFFFFFu, m, o));
    if ((tid & 31) == 0) red[tid >> 5] = m;
    __syncthreads();
    m = red[0];
#pragma unroll
    for (int w = 1; w < 8; w++) m = fmaxf(m, red[w]);
    __syncthreads();

    float s = 0.f;
#pragma unroll
    for (int i = 0; i < 8; i++) { v[i] = __expf(v[i] - m); s += v[i]; }
#pragma unroll
    for (int o = 16; o > 0; o >>= 1) s += __shfl_xor_sync(0xFFFFFFFFu, s, o);
    if ((tid & 31) == 0) red[tid >> 5] = s;
    __syncthreads();
    s = red[0];
#pragma unroll
    for (int w = 1; w < 8; w++) s += red[w];

    float inv = 1.f / s;
#pragma unroll
    for (int i = 0; i < 8; i++) gst(attn, rbase + tid + i * 256, ATTN_ELEMS, v[i] * inv);
}

// ---------------------------------------------------------------------------
// AV: g_ctx[bh,i,d] = sum_k attn[bh,i,k] * g_v[bh,k,d].  grid (S/64, B*H).
// ---------------------------------------------------------------------------
__global__ void __launch_bounds__(256) av_kernel(const float* __restrict__ attn)
{
    __shared__ float Ps[64][65];
    __shared__ float Vs[64][65];

    const int tx = threadIdx.x, ty = threadIdx.y;
    const int tid = ty * 16 + tx;
    const int bh = blockIdx.y;
    const int row0 = blockIdx.x * 64;
    const long long pbase = (long long)bh * SS * SS;
    const long long vbase = (long long)bh * SS * DH;

    float acc[4][4];
#pragma unroll
    for (int i = 0; i < 4; i++)
#pragma unroll
        for (int j = 0; j < 4; j++) acc[i][j] = 0.f;

    for (int kk = 0; kk < SS; kk += 64) {
#pragma unroll
        for (int l = 0; l < 16; l++) {
            int idx = tid + l * 256;
            int r = idx >> 6, c = idx & 63;
            Ps[r][c] = gld(attn, pbase + (long long)(row0 + r) * SS + kk + c, ATTN_ELEMS);
            Vs[r][c] = gld(g_v, vbase + (long long)(kk + r) * DH + c, QKV_ELEMS);
        }
        __syncthreads();
#pragma unroll
        for (int k = 0; k < 64; k++) {
            float a[4], b[4];
#pragma unroll
            for (int i = 0; i < 4; i++) a[i] = Ps[ty * 4 + i][k];
#pragma unroll
            for (int j = 0; j < 4; j++) b[j] = Vs[k][tx * 4 + j];
#pragma unroll
            for (int i = 0; i < 4; i++)
#pragma unroll
                for (int j = 0; j < 4; j++) acc[i][j] += a[i] * b[j];
        }
        __syncthreads();
    }

#pragma unroll
    for (int i = 0; i < 4; i++) {
        long long obase = vbase + (long long)(row0 + ty * 4 + i) * DH;
#pragma unroll
        for (int j = 0; j < 4; j++)
            gst(g_ctx, obase + tx * 4 + j, QKV_ELEMS, acc[i][j]);
    }
}

// ---------------------------------------------------------------------------
static bool s_capturing_probe()
{
    cudaStreamCaptureStatus st = cudaStreamCaptureStatusNone;
    cudaError_t e = cudaStreamIsCapturing(0, &st);
    if (e != cudaSuccess) { cudaGetLastError(); return true; }  // be safe: no syncs
    return st != cudaStreamCaptureStatusNone;
}

static void diag(const char* name, bool capturing)
{
    if (capturing) return;  // keep graph capture pure (launches only)
    cudaError_t e = cudaDeviceSynchronize();
    fprintf(stderr, "[klaunch] %s: %s\n", name, cudaGetErrorString(e));
    cudaGetLastError();
}

extern "C" void kernel_launch(void* const* d_in, const int* in_sizes, int n_in,
                              void* d_out, int out_size)
{
    // Confirmed layout (round-4 diagnostics): signature order, element counts.
    const float* query = (const float*)d_in[0];
    const float* key   = (const float*)d_in[1];
    const float* value = (const float*)d_in[2];
    const float* W_q   = (const float*)d_in[3];
    const float* b_q   = (const float*)d_in[4];
    const float* W_k   = (const float*)d_in[5];
    const float* b_k   = (const float*)d_in[6];
    const float* W_v   = (const float*)d_in[7];
    const float* b_v   = (const float*)d_in[8];
    const float* W_o   = (const float*)d_in[9];
    const float* b_o   = (const float*)d_in[10];

    float* out  = (float*)d_out;
    float* attn = out + OUT_ELEMS;  // out_size == OUT_ELEMS + ATTN_ELEMS (confirmed)

    const bool capturing = s_capturing_probe();

    dim3 thr(16, 16);
    dim3 gProj(DM / 64, MM / 64);             // (12, 64)
    dim3 gScores(SS / 64, SS / 64, BB * HH);  // (32, 32, 24)
    dim3 gAV(SS / 64, BB * HH);               // (32, 24)

    proj_kernel<0><<<gProj, thr>>>(query, W_q, b_q);
    diag("proj_q", capturing);
    proj_kernel<1><<<gProj, thr>>>(key, W_k, b_k);
    diag("proj_k", capturing);
    proj_kernel<2><<<gProj, thr>>>(value, W_v, b_v);
    diag("proj_v", capturing);

    scores_kernel<<<gScores, thr>>>(attn);
    diag("scores", capturing);

    softmax_kernel<<<BB * HH * SS, 256>>>(attn);
    diag("softmax", capturing);

    av_kernel<<<gAV, thr>>>(attn);
    diag("av", capturing);

    out_proj_kernel<<<gProj, thr>>>(W_o, b_o, out);
    diag("out_proj", capturing);
}

// round 6
// speedup vs baseline: 1.2873x; 1.2873x over previous
#include <cuda_runtime.h>
#include <cstdio>

#define BB 2
#define HH 12
#define SS 2048
#define DH 64
#define DM 768
#define MM (BB * SS)                                   // 4096
#define ACT_ELEMS ((long long)BB * SS * DM)            // 3,145,728
#define QKV_ELEMS ((long long)BB * HH * SS * DH)       // 3,145,728
#define W_ELEMS ((long long)DM * DM)                   // 589,824
#define OUT_ELEMS ((long long)BB * SS * DM)            // 3,145,728
#define ATTN_ELEMS ((long long)BB * HH * SS * SS)      // 100,663,296

// Static device scratch (module-load allocated; no runtime allocs).
__device__ __align__(16) float g_q[3145728];
__device__ __align__(16) float g_k[3145728];
__device__ __align__(16) float g_v[3145728];
__device__ __align__(16) float g_ctx[3145728];

// Guarded global accessors (proven shell from round 5).
__device__ __forceinline__ float gld(const float* __restrict__ p, long long i, long long n) {
    return (i >= 0 && i < n) ? __ldg(p + i) : 0.f;
}
__device__ __forceinline__ void gst(float* __restrict__ p, long long i, long long n, float v) {
    if (i >= 0 && i < n) p[i] = v;
}
__device__ __forceinline__ float4 gld4(const float* __restrict__ p, long long i, long long n) {
    if (i >= 0 && i + 3 < n) return __ldg((const float4*)(p + i));
    float4 z = {0.f, 0.f, 0.f, 0.f};
    return z;
}

// ===========================================================================
// Projection GEMM: C(head layout) = A[M,K] @ W[N,K]^T + bias.
// Tile 128m x 64n, BK=16, 256 threads, micro 8x4, k-major smem (LDS.128).
// DSTSEL: 0->g_q, 1->g_k, 2->g_v.
// ===========================================================================
template <int DSTSEL>
__global__ void __launch_bounds__(256) proj_kernel(
    const float* __restrict__ A, const float* __restrict__ W,
    const float* __restrict__ bias)
{
    __shared__ float As[16][132];   // [k][m]
    __shared__ float Ws[16][68];    // [k][n]

    float* C = (DSTSEL == 0) ? g_q : (DSTSEL == 1) ? g_k : g_v;

    const int tid = threadIdx.x;
    const int tx = tid & 15;        // n: tx*4
    const int ty = tid >> 4;        // m: ty*8
    const int row0 = blockIdx.y * 128;
    const int col0 = blockIdx.x * 64;

    float acc[8][4];
#pragma unroll
    for (int i = 0; i < 8; i++)
#pragma unroll
        for (int j = 0; j < 4; j++) acc[i][j] = 0.f;

    for (int k0 = 0; k0 < DM; k0 += 16) {
#pragma unroll
        for (int it = 0; it < 2; it++) {
            int v = tid + it * 256;
            int kg = v & 3, m = v >> 2;   // m 0..127, kg 0..3
            float4 a = gld4(A, (long long)(row0 + m) * DM + k0 + kg * 4, ACT_ELEMS);
            As[kg * 4 + 0][m] = a.x; As[kg * 4 + 1][m] = a.y;
            As[kg * 4 + 2][m] = a.z; As[kg * 4 + 3][m] = a.w;
        }
        {
            int kg = tid & 3, n = tid >> 2;  // n 0..63
            float4 w = gld4(W, (long long)(col0 + n) * DM + k0 + kg * 4, W_ELEMS);
            Ws[kg * 4 + 0][n] = w.x; Ws[kg * 4 + 1][n] = w.y;
            Ws[kg * 4 + 2][n] = w.z; Ws[kg * 4 + 3][n] = w.w;
        }
        __syncthreads();

#pragma unroll
        for (int k = 0; k < 16; k++) {
            float4 a0 = *(const float4*)&As[k][ty * 8];
            float4 a1 = *(const float4*)&As[k][ty * 8 + 4];
            float4 bb = *(const float4*)&Ws[k][tx * 4];
            float a_[8] = {a0.x, a0.y, a0.z, a0.w, a1.x, a1.y, a1.z, a1.w};
            float b_[4] = {bb.x, bb.y, bb.z, bb.w};
#pragma unroll
            for (int i = 0; i < 8; i++)
#pragma unroll
                for (int j = 0; j < 4; j++) acc[i][j] += a_[i] * b_[j];
        }
        __syncthreads();
    }

#pragma unroll
    for (int i = 0; i < 8; i++) {
        int gm = row0 + ty * 8 + i;
        int b = gm >> 11, s = gm & 2047;
#pragma unroll
        for (int j = 0; j < 4; j++) {
            int gn = col0 + tx * 4 + j;
            int h = gn >> 6, d = gn & 63;
            long long ci = (((long long)(b * HH + h)) * SS + s) * DH + d;
            gst(C, ci, QKV_ELEMS, acc[i][j] + gld(bias, gn, DM));
        }
    }
}

// ===========================================================================
// Output projection: out = gather(g_ctx) @ W_o^T + b_o.  Same tiling.
// ===========================================================================
__global__ void __launch_bounds__(256) out_proj_kernel(
    const float* __restrict__ W, const float* __restrict__ bias,
    float* __restrict__ out)
{
    __shared__ float As[16][132];
    __shared__ float Ws[16][68];

    const int tid = threadIdx.x;
    const int tx = tid & 15;
    const int ty = tid >> 4;
    const int row0 = blockIdx.y * 128;
    const int col0 = blockIdx.x * 64;

    float acc[8][4];
#pragma unroll
    for (int i = 0; i < 8; i++)
#pragma unroll
        for (int j = 0; j < 4; j++) acc[i][j] = 0.f;

    for (int k0 = 0; k0 < DM; k0 += 16) {
#pragma unroll
        for (int it = 0; it < 2; it++) {
            int v = tid + it * 256;
            int kg = v & 3, m = v >> 2;
            int gm = row0 + m;
            int gk = k0 + kg * 4;               // 4-aligned, stays inside one head
            int b = gm >> 11, s = gm & 2047;
            int h = gk >> 6, d = gk & 63;
            float4 a = gld4(g_ctx, (((long long)(b * HH + h)) * SS + s) * DH + d, QKV_ELEMS);
            As[kg * 4 + 0][m] = a.x; As[kg * 4 + 1][m] = a.y;
            As[kg * 4 + 2][m] = a.z; As[kg * 4 + 3][m] = a.w;
        }
        {
            int kg = tid & 3, n = tid >> 2;
            float4 w = gld4(W, (long long)(col0 + n) * DM + k0 + kg * 4, W_ELEMS);
            Ws[kg * 4 + 0][n] = w.x; Ws[kg * 4 + 1][n] = w.y;
            Ws[kg * 4 + 2][n] = w.z; Ws[kg * 4 + 3][n] = w.w;
        }
        __syncthreads();

#pragma unroll
        for (int k = 0; k < 16; k++) {
            float4 a0 = *(const float4*)&As[k][ty * 8];
            float4 a1 = *(const float4*)&As[k][ty * 8 + 4];
            float4 bb = *(const float4*)&Ws[k][tx * 4];
            float a_[8] = {a0.x, a0.y, a0.z, a0.w, a1.x, a1.y, a1.z, a1.w};
            float b_[4] = {bb.x, bb.y, bb.z, bb.w};
#pragma unroll
            for (int i = 0; i < 8; i++)
#pragma unroll
                for (int j = 0; j < 4; j++) acc[i][j] += a_[i] * b_[j];
        }
        __syncthreads();
    }

#pragma unroll
    for (int i = 0; i < 8; i++) {
        int gm = row0 + ty * 8 + i;
#pragma unroll
        for (int j = 0; j < 4; j++) {
            int gn = col0 + tx * 4 + j;
            gst(out, (long long)gm * DM + gn, OUT_ELEMS, acc[i][j] + gld(bias, gn, DM));
        }
    }
}

// ===========================================================================
// Scores: attn[bh,i,j] = dot(Q[i,:], K[j,:]) / 8.
// Tile 128q x 64kcol, K=64 in 2 chunks of 32. grid (S/64, S/128, B*H).
// ===========================================================================
__global__ void __launch_bounds__(256) scores_kernel(float* __restrict__ attn)
{
    __shared__ float Qs[32][132];   // [k][q]
    __shared__ float Ks[32][68];    // [k][kcol]

    const int tid = threadIdx.x;
    const int tx = tid & 15;
    const int ty = tid >> 4;
    const int bh = blockIdx.z;
    const int row0 = blockIdx.y * 128;  // q
    const int col0 = blockIdx.x * 64;   // k-col
    const long long qbase = (long long)bh * SS * DH;

    float acc[8][4];
#pragma unroll
    for (int i = 0; i < 8; i++)
#pragma unroll
        for (int j = 0; j < 4; j++) acc[i][j] = 0.f;

#pragma unroll
    for (int kc = 0; kc < DH; kc += 32) {
#pragma unroll
        for (int it = 0; it < 4; it++) {
            int v = tid + it * 256;          // 0..1023
            int kg = v & 7, m = v >> 3;      // kg 0..7, m 0..127
            float4 a = gld4(g_q, qbase + (long long)(row0 + m) * DH + kc + kg * 4, QKV_ELEMS);
            Qs[kg * 4 + 0][m] = a.x; Qs[kg * 4 + 1][m] = a.y;
            Qs[kg * 4 + 2][m] = a.z; Qs[kg * 4 + 3][m] = a.w;
        }
#pragma unroll
        for (int it = 0; it < 2; it++) {
            int v = tid + it * 256;          // 0..511
            int kg = v & 7, n = v >> 3;      // n 0..63
            float4 a = gld4(g_k, qbase + (long long)(col0 + n) * DH + kc + kg * 4, QKV_ELEMS);
            Ks[kg * 4 + 0][n] = a.x; Ks[kg * 4 + 1][n] = a.y;
            Ks[kg * 4 + 2][n] = a.z; Ks[kg * 4 + 3][n] = a.w;
        }
        __syncthreads();

#pragma unroll
        for (int k = 0; k < 32; k++) {
            float4 a0 = *(const float4*)&Qs[k][ty * 8];
            float4 a1 = *(const float4*)&Qs[k][ty * 8 + 4];
            float4 bb = *(const float4*)&Ks[k][tx * 4];
            float a_[8] = {a0.x, a0.y, a0.z, a0.w, a1.x, a1.y, a1.z, a1.w};
            float b_[4] = {bb.x, bb.y, bb.z, bb.w};
#pragma unroll
            for (int i = 0; i < 8; i++)
#pragma unroll
                for (int j = 0; j < 4; j++) acc[i][j] += a_[i] * b_[j];
        }
        __syncthreads();
    }

#pragma unroll
    for (int i = 0; i < 8; i++) {
        long long rbase = ((long long)bh * SS + row0 + ty * 8 + i) * SS + col0;
#pragma unroll
        for (int j = 0; j < 4; j++)
            gst(attn, rbase + tx * 4 + j, ATTN_ELEMS, acc[i][j] * 0.125f);
    }
}

// ===========================================================================
// Row softmax over 2048 cols; one 256-thread block per row; float4 I/O.
// ===========================================================================
__global__ void __launch_bounds__(256) softmax_kernel(float* __restrict__ attn)
{
    __shared__ float red[8];
    const long long rbase = (long long)blockIdx.x * SS;
    const int tid = threadIdx.x;

    float4 v0 = gld4(attn, rbase + tid * 4, ATTN_ELEMS);
    float4 v1 = gld4(attn, rbase + 1024 + tid * 4, ATTN_ELEMS);

    float m = fmaxf(fmaxf(fmaxf(v0.x, v0.y), fmaxf(v0.z, v0.w)),
                    fmaxf(fmaxf(v1.x, v1.y), fmaxf(v1.z, v1.w)));
#pragma unroll
    for (int o = 16; o > 0; o >>= 1) m = fmaxf(m, __shfl_xor_sync(0xFFFFFFFFu, m, o));
    if ((tid & 31) == 0) red[tid >> 5] = m;
    __syncthreads();
    m = red[0];
#pragma unroll
    for (int w = 1; w < 8; w++) m = fmaxf(m, red[w]);
    __syncthreads();

    v0.x = __expf(v0.x - m); v0.y = __expf(v0.y - m);
    v0.z = __expf(v0.z - m); v0.w = __expf(v0.w - m);
    v1.x = __expf(v1.x - m); v1.y = __expf(v1.y - m);
    v1.z = __expf(v1.z - m); v1.w = __expf(v1.w - m);
    float s = v0.x + v0.y + v0.z + v0.w + v1.x + v1.y + v1.z + v1.w;
#pragma unroll
    for (int o = 16; o > 0; o >>= 1) s += __shfl_xor_sync(0xFFFFFFFFu, s, o);
    if ((tid & 31) == 0) red[tid >> 5] = s;
    __syncthreads();
    s = red[0];
#pragma unroll
    for (int w = 1; w < 8; w++) s += red[w];

    float inv = 1.f / s;
    v0.x *= inv; v0.y *= inv; v0.z *= inv; v0.w *= inv;
    v1.x *= inv; v1.y *= inv; v1.z *= inv; v1.w *= inv;

    long long i0 = rbase + tid * 4;
    long long i1 = rbase + 1024 + tid * 4;
    if (i0 + 3 < ATTN_ELEMS) *(float4*)(attn + i0) = v0;
    if (i1 + 3 < ATTN_ELEMS) *(float4*)(attn + i1) = v1;
}

// ===========================================================================
// AV: g_ctx[bh,i,d] = sum_k attn[bh,i,k] * g_v[bh,k,d].
// Tile 128q x 64d, BK=32 (64 chunks). grid (S/128, B*H).
// ===========================================================================
__global__ void __launch_bounds__(256) av_kernel(const float* __restrict__ attn)
{
    __shared__ float Ps[32][132];   // [k][q]
    __shared__ float Vs[32][68];    // [k][d]

    const int tid = threadIdx.x;
    const int tx = tid & 15;
    const int ty = tid >> 4;
    const int bh = blockIdx.y;
    const int row0 = blockIdx.x * 128;
    const long long pbase = (long long)bh * SS * SS;
    const long long vbase = (long long)bh * SS * DH;

    float acc[8][4];
#pragma unroll
    for (int i = 0; i < 8; i++)
#pragma unroll
        for (int j = 0; j < 4; j++) acc[i][j] = 0.f;

    for (int kk = 0; kk < SS; kk += 32) {
#pragma unroll
        for (int it = 0; it < 4; it++) {
            int v = tid + it * 256;
            int kg = v & 7, m = v >> 3;      // m 0..127
            float4 a = gld4(attn, pbase + (long long)(row0 + m) * SS + kk + kg * 4, ATTN_ELEMS);
            Ps[kg * 4 + 0][m] = a.x; Ps[kg * 4 + 1][m] = a.y;
            Ps[kg * 4 + 2][m] = a.z; Ps[kg * 4 + 3][m] = a.w;
        }
#pragma unroll
        for (int it = 0; it < 2; it++) {
            int v = tid + it * 256;          // 0..511
            int k = v >> 4, dg = v & 15;     // k 0..31, dg 0..15
            float4 a = gld4(g_v, vbase + (long long)(kk + k) * DH + dg * 4, QKV_ELEMS);
            *(float4*)&Vs[k][dg * 4] = a;
        }
        __syncthreads();

#pragma unroll
        for (int k = 0; k < 32; k++) {
            float4 a0 = *(const float4*)&Ps[k][ty * 8];
            float4 a1 = *(const float4*)&Ps[k][ty * 8 + 4];
            float4 bb = *(const float4*)&Vs[k][tx * 4];
            float a_[8] = {a0.x, a0.y, a0.z, a0.w, a1.x, a1.y, a1.z, a1.w};
            float b_[4] = {bb.x, bb.y, bb.z, bb.w};
#pragma unroll
            for (int i = 0; i < 8; i++)
#pragma unroll
                for (int j = 0; j < 4; j++) acc[i][j] += a_[i] * b_[j];
        }
        __syncthreads();
    }

#pragma unroll
    for (int i = 0; i < 8; i++) {
        long long obase = vbase + (long long)(row0 + ty * 8 + i) * DH;
#pragma unroll
        for (int j = 0; j < 4; j++)
            gst(g_ctx, obase + tx * 4 + j, QKV_ELEMS, acc[i][j]);
    }
}

// ---------------------------------------------------------------------------
static bool s_capturing_probe()
{
    cudaStreamCaptureStatus st = cudaStreamCaptureStatusNone;
    cudaError_t e = cudaStreamIsCapturing(0, &st);
    if (e != cudaSuccess) { cudaGetLastError(); return true; }
    return st != cudaStreamCaptureStatusNone;
}

static void diag(const char* name, bool capturing)
{
    if (capturing) return;  // launches only during graph capture
    cudaError_t e = cudaDeviceSynchronize();
    fprintf(stderr, "[klaunch] %s: %s\n", name, cudaGetErrorString(e));
    cudaGetLastError();
}

extern "C" void kernel_launch(void* const* d_in, const int* in_sizes, int n_in,
                              void* d_out, int out_size)
{
    const float* query = (const float*)d_in[0];
    const float* key   = (const float*)d_in[1];
    const float* value = (const float*)d_in[2];
    const float* W_q   = (const float*)d_in[3];
    const float* b_q   = (const float*)d_in[4];
    const float* W_k   = (const float*)d_in[5];
    const float* b_k   = (const float*)d_in[6];
    const float* W_v   = (const float*)d_in[7];
    const float* b_v   = (const float*)d_in[8];
    const float* W_o   = (const float*)d_in[9];
    const float* b_o   = (const float*)d_in[10];

    float* out  = (float*)d_out;
    float* attn = out + OUT_ELEMS;  // confirmed: out_size == OUT_ELEMS + ATTN_ELEMS

    const bool capturing = s_capturing_probe();

    dim3 gProj(DM / 64, MM / 128);             // (12, 32)
    dim3 gScores(SS / 64, SS / 128, BB * HH);  // (32, 16, 24)
    dim3 gAV(SS / 128, BB * HH);               // (16, 24)

    proj_kernel<0><<<gProj, 256>>>(query, W_q, b_q);
    diag("proj_q", capturing);
    proj_kernel<1><<<gProj, 256>>>(key, W_k, b_k);
    diag("proj_k", capturing);
    proj_kernel<2><<<gProj, 256>>>(value, W_v, b_v);
    diag("proj_v", capturing);

    scores_kernel<<<gScores, 256>>>(attn);
    diag("scores", capturing);

    softmax_kernel<<<BB * HH * SS, 256>>>(attn);
    diag("softmax", capturing);

    av_kernel<<<gAV, 256>>>(attn);
    diag("av", capturing);

    out_proj_kernel<<<gProj, 256>>>(W_o, b_o, out);
    diag("out_proj", capturing);
}